// round 1
// baseline (speedup 1.0000x reference)
#include <cuda_runtime.h>
#include <cstdint>

// Sparse embedding-bag:
//   out[b, :] = bias + sum_k weight[ft_ics[b,k], :] * ft_vals[b,k]
// B=16384, K=32, N_OUT=256, table 41024x256 fp32 (42 MB -> L2 resident).
//
// Layout: block = (64, 4). threadIdx.x = output float4 column (64 * 4 = 256 cols),
// threadIdx.y = batch row within block. grid = B/4 blocks.
// Each thread keeps a float4 accumulator; weight rows are read as coalesced
// LDG.128. Indices/vals staged through shared memory once per row.

#define K_FEATS 32
#define ROWS_PER_BLOCK 4
#define COL4 64  // 256 / 4

__global__ __launch_bounds__(COL4 * ROWS_PER_BLOCK, 8)
void ft_embed_bag_kernel(const int* __restrict__ ics,
                         const float* __restrict__ vals,
                         const float4* __restrict__ weight,   // [N_IN][64] float4
                         const float4* __restrict__ bias,     // [64] float4
                         float4* __restrict__ out)            // [B][64] float4
{
    __shared__ int   s_idx[ROWS_PER_BLOCK][K_FEATS];
    __shared__ float s_val[ROWS_PER_BLOCK][K_FEATS];

    const int ty = threadIdx.y;
    const int tx = threadIdx.x;
    const int b  = blockIdx.x * ROWS_PER_BLOCK + ty;

    // Stage this row's indices/values (32 each) via first 32 lanes of the row-group.
    if (tx < K_FEATS) {
        s_idx[ty][tx] = ics[b * K_FEATS + tx];
        s_val[ty][tx] = vals[b * K_FEATS + tx];
    }
    __syncthreads();

    float4 acc = bias[tx];

    // Unroll x4 -> 4 independent LDG.128 in flight per thread per iteration.
    #pragma unroll 4
    for (int k = 0; k < K_FEATS; ++k) {
        const int idx = s_idx[ty][k];
        if (idx < 0) continue;                    // padding guard (never taken here)
        const float  v  = s_val[ty][k];
        const float4 wv = __ldg(&weight[(size_t)idx * COL4 + tx]);
        acc.x = fmaf(v, wv.x, acc.x);
        acc.y = fmaf(v, wv.y, acc.y);
        acc.z = fmaf(v, wv.z, acc.z);
        acc.w = fmaf(v, wv.w, acc.w);
    }

    out[(size_t)b * COL4 + tx] = acc;
}

extern "C" void kernel_launch(void* const* d_in, const int* in_sizes, int n_in,
                              void* d_out, int out_size)
{
    const int*    ics    = (const int*)d_in[0];
    const float*  vals   = (const float*)d_in[1];
    const float4* weight = (const float4*)d_in[2];
    const float4* bias   = (const float4*)d_in[3];
    float4*       out    = (float4*)d_out;

    const int B = in_sizes[0] / K_FEATS;  // 16384

    dim3 block(COL4, ROWS_PER_BLOCK);
    dim3 grid(B / ROWS_PER_BLOCK);
    ft_embed_bag_kernel<<<grid, block>>>(ics, vals, weight, bias, out);
}